// round 10
// baseline (speedup 1.0000x reference)
#include <cuda_runtime.h>
#include <cstdint>

#define N_SRC 65536
#define N_DST 8192
#define MAXN  32
#define H     128
#define NPC   8          // nodes per CTA in attn

typedef unsigned long long ULL;

// ---------------- f32x2 helpers ----------------
__device__ __forceinline__ void ffma2(ULL& d, ULL a, ULL b) {
    asm("fma.rn.f32x2 %0, %1, %2, %3;" : "=l"(d) : "l"(a), "l"(b), "l"(d));
}
__device__ __forceinline__ ULL pk2(float x, float y) {
    ULL r; asm("mov.b64 %0, {%1, %2};" : "=l"(r) : "f"(x), "f"(y)); return r;
}
__device__ __forceinline__ float2 upk2(ULL v) {
    float2 f; asm("mov.b64 {%0, %1}, %2;" : "=f"(f.x), "=f"(f.y) : "l"(v)); return f;
}

// ---------------- tf32 mma helpers ----------------
__device__ __forceinline__ uint32_t tf32r(float x) {
    uint32_t r; asm("cvt.rna.tf32.f32 %0, %1;" : "=r"(r) : "f"(x)); return r;
}
__device__ __forceinline__ void mma_tf32(float& d0, float& d1, float& d2, float& d3,
    uint32_t a0, uint32_t a1, uint32_t a2, uint32_t a3, uint32_t b0, uint32_t b1)
{
    asm volatile("mma.sync.aligned.m16n8k8.row.col.f32.tf32.tf32.f32 "
        "{%0,%1,%2,%3}, {%4,%5,%6,%7}, {%8,%9}, {%0,%1,%2,%3};"
        : "+f"(d0), "+f"(d1), "+f"(d2), "+f"(d3)
        : "r"(a0), "r"(a1), "r"(a2), "r"(a3), "r"(b0), "r"(b1));
}

// ---------------- cp.async helpers ----------------
__device__ __forceinline__ uint32_t sptr(const void* p) {
    return (uint32_t)__cvta_generic_to_shared(p);
}
__device__ __forceinline__ void cp16(uint32_t dst, const void* src) {
    asm volatile("cp.async.cg.shared.global [%0], [%1], 16;" :: "r"(dst), "l"(src));
}
__device__ __forceinline__ void cp_commit() {
    asm volatile("cp.async.commit_group;");
}
__device__ __forceinline__ void cp_wait_all() {
    asm volatile("cp.async.wait_group 0;");
}

// ---------------- scratch ----------------
__device__ __align__(16) float g_feat_sim[N_SRC * H];
__device__ __align__(16) float g_feat_cor[N_SRC * H];
__device__ __align__(16) float g_rst_sim[N_DST * H];
__device__ __align__(16) float g_rst_cor[N_DST * H];
__device__ __align__(16) float g_H1[H * H];
__device__ __align__(16) float g_H2[H * H];
__device__ __align__(16) float g_M[256 * 256];
__device__ __align__(16) float g_c[256];

// ---------------- feat: [emb0[x0]|emb1[x1]] @ W_in + b, both modes ----------------
__global__ __launch_bounds__(128) void feat_kernel(
    const int* __restrict__ x,
    const float* __restrict__ e0s, const float* __restrict__ e1s,
    const float* __restrict__ Ws,  const float* __restrict__ bs, float* __restrict__ outs,
    const float* __restrict__ e0c, const float* __restrict__ e1c,
    const float* __restrict__ Wc,  const float* __restrict__ bc, float* __restrict__ outc)
{
    __shared__ float xb[H][66];
    __shared__ int2  xs[64];

    const int halfgrid = N_SRC / 64;
    const bool is_sim = blockIdx.x < halfgrid;
    const int  blk    = is_sim ? blockIdx.x : blockIdx.x - halfgrid;
    const float* emb0 = is_sim ? e0s : e0c;
    const float* emb1 = is_sim ? e1s : e1c;
    const float* W    = is_sim ? Ws  : Wc;
    const float* b    = is_sim ? bs  : bc;
    float*       out  = is_sim ? outs : outc;

    const int base = blk * 64;
    const int tid = threadIdx.x;

    if (tid < 64) xs[tid] = ((const int2*)x)[base + tid];
    __syncthreads();

    {
        const int k = tid;
        if (k < 32) {
#pragma unroll 8
            for (int r = 0; r < 64; r++)
                xb[k][r] = emb0[xs[r].x * 32 + k];
        } else {
#pragma unroll 8
            for (int r = 0; r < 64; r++)
                xb[k][r] = emb1[xs[r].y * 96 + (k - 32)];
        }
    }
    __syncthreads();

    const int jj = tid & 63;
    const int half = tid >> 6;
    const int j0 = jj, j1 = jj + 64;

    ULL acc0[16], acc1[16];
#pragma unroll
    for (int rp = 0; rp < 16; rp++) { acc0[rp] = 0ULL; acc1[rp] = 0ULL; }

#pragma unroll 2
    for (int k = 0; k < H; k++) {
        const float w0 = W[k * H + j0];
        const float w1 = W[k * H + j1];
        const ULL wd0 = pk2(w0, w0);
        const ULL wd1 = pk2(w1, w1);
        const ULL* xp = (const ULL*)&xb[k][half * 32];
#pragma unroll
        for (int rp = 0; rp < 16; rp++) {
            const ULL xv = xp[rp];
            ffma2(acc0[rp], xv, wd0);
            ffma2(acc1[rp], xv, wd1);
        }
    }
    const float b0 = b[j0], b1 = b[j1];
    const int rbase = base + half * 32;
#pragma unroll
    for (int rp = 0; rp < 16; rp++) {
        const float2 f0 = upk2(acc0[rp]);
        const float2 f1 = upk2(acc1[rp]);
        out[(rbase + 2 * rp + 0) * H + j0] = f0.x + b0;
        out[(rbase + 2 * rp + 1) * H + j0] = f0.y + b0;
        out[(rbase + 2 * rp + 0) * H + j1] = f1.x + b1;
        out[(rbase + 2 * rp + 1) * H + j1] = f1.y + b1;
    }
}

// ---------------- attn smem layout (dynamic) ----------------
struct AttnSmem {
    float DQ[2][2][32][132];   // [buf][0=D,1=Q][row][col]
    float hs[2][128];          // h_self row, double buffered
    float Es[32][33];
    float invcol[32];
    float invrow[32];
    float wv[32];
    float vv[32];
    float coef[32];
    float O[3 * H];
};
#define ATTN_SMEM ((int)sizeof(AttnSmem))

// ---------------- co-attention pool: pipelined multi-node CTA ----------------
// 256 threads; NPC nodes per CTA; cp.async double-buffered gather.
__global__ __launch_bounds__(256) void attn_kernel(
    const float* __restrict__ feat_sim, const float* __restrict__ feat_cor,
    const int* __restrict__ neigh_sim, const int* __restrict__ neigh_cor,
    float* __restrict__ rst_sim, float* __restrict__ rst_cor)
{
    extern __shared__ char smem_raw[];
    AttnSmem& S = *reinterpret_cast<AttnSmem*>(smem_raw);

    const int halfgrid = N_DST / NPC;
    const bool is_sim = blockIdx.x < halfgrid;
    const int  blk    = is_sim ? blockIdx.x : blockIdx.x - halfgrid;
    const float* feat = is_sim ? feat_sim : feat_cor;
    const int* idxD = is_sim ? neigh_cor : neigh_sim;   // sim: D = nf_cor
    const int* idxQ = is_sim ? neigh_sim : neigh_cor;
    float*     rst  = is_sim ? rst_sim : rst_cor;

    const int tid = threadIdx.x;
    const int lane = tid & 31;
    const int w = tid >> 5;
    const int base = blk * NPC;

    // index regs for the node about to be gathered
    int pD[4], pQ[4];

    // load idx(node base)
#pragma unroll
    for (int i = 0; i < 4; i++) {
        const int r = w * 4 + i;
        pD[i] = idxD[base * 32 + r];
        pQ[i] = idxQ[base * 32 + r];
    }
    // issue gather(node base) -> buf 0
    {
#pragma unroll
        for (int i = 0; i < 4; i++) {
            const int r = w * 4 + i;
            cp16(sptr(&S.DQ[0][0][r][lane * 4]), feat + (size_t)pD[i] * H + lane * 4);
            cp16(sptr(&S.DQ[0][1][r][lane * 4]), feat + (size_t)pQ[i] * H + lane * 4);
        }
        if (w == 0) cp16(sptr(&S.hs[0][lane * 4]), feat + (size_t)base * H + lane * 4);
        cp_commit();
    }
    // load idx(node base+1)
#pragma unroll
    for (int i = 0; i < 4; i++) {
        const int r = w * 4 + i;
        pD[i] = idxD[(base + 1) * 32 + r];
        pQ[i] = idxQ[(base + 1) * 32 + r];
    }

    for (int it = 0; it < NPC; ++it) {
        const int node = base + it;
        const int b = it & 1;

        cp_wait_all();
        __syncthreads();

        // issue gather for node it+1 into other buffer, then prefetch idx it+2
        if (it + 1 < NPC) {
            const int nb = b ^ 1;
#pragma unroll
            for (int i = 0; i < 4; i++) {
                const int r = w * 4 + i;
                cp16(sptr(&S.DQ[nb][0][r][lane * 4]), feat + (size_t)pD[i] * H + lane * 4);
                cp16(sptr(&S.DQ[nb][1][r][lane * 4]), feat + (size_t)pQ[i] * H + lane * 4);
            }
            if (w == 0) cp16(sptr(&S.hs[nb][lane * 4]), feat + (size_t)(node + 1) * H + lane * 4);
            cp_commit();
            if (it + 2 < NPC) {
#pragma unroll
                for (int i = 0; i < 4; i++) {
                    const int r = w * 4 + i;
                    pD[i] = idxD[(node + 2) * 32 + r];
                    pQ[i] = idxQ[(node + 2) * 32 + r];
                }
            }
        }

        // ---- L via tf32 MMA, then E = exp(L) ----
        {
            const int mt = w & 1;
            const int nt = w >> 1;
            const int gid = lane >> 2;
            const int tig = lane & 3;
            const int rA0 = mt * 16 + gid;
            const int rA1 = rA0 + 8;
            const int cn  = nt * 8 + gid;

            float c0 = 0.f, c1 = 0.f, c2 = 0.f, c3 = 0.f;
#pragma unroll
            for (int kc = 0; kc < 16; kc++) {
                const int k0 = kc * 8;
                const uint32_t a0 = tf32r(S.DQ[b][0][rA0][k0 + tig]);
                const uint32_t a1 = tf32r(S.DQ[b][0][rA1][k0 + tig]);
                const uint32_t a2 = tf32r(S.DQ[b][0][rA0][k0 + tig + 4]);
                const uint32_t a3 = tf32r(S.DQ[b][0][rA1][k0 + tig + 4]);
                const uint32_t b0 = tf32r(S.DQ[b][1][cn][k0 + tig]);
                const uint32_t b1 = tf32r(S.DQ[b][1][cn][k0 + tig + 4]);
                mma_tf32(c0, c1, c2, c3, a0, a1, a2, a3, b0, b1);
            }
            const int ec = nt * 8 + 2 * tig;
            S.Es[rA0][ec]     = __expf(c0);
            S.Es[rA0][ec + 1] = __expf(c1);
            S.Es[rA1][ec]     = __expf(c2);
            S.Es[rA1][ec + 1] = __expf(c3);
        }
        __syncthreads();

        // ---- stats ----
        if (w == 0) {
            const int m = lane;
            float s = 0.f;
#pragma unroll
            for (int k = 0; k < 32; k++) s += S.Es[m][k];
            S.invrow[m] = __frcp_rn(s);
        } else if (w == 1) {
            const int k = lane;
            float s = 0.f;
#pragma unroll
            for (int m = 0; m < 32; m++) s += S.Es[m][k];
            S.invcol[k] = __frcp_rn(s);
        }
        __syncthreads();

        if (w == 0) {
            const int m = lane;
            float s = 0.f;
#pragma unroll
            for (int k = 0; k < 32; k++) s += S.Es[m][k] * S.invcol[k];
            S.wv[m] = s;
            S.coef[m] = s * S.invrow[m];
        }
        __syncthreads();

        if (w == 1) {
            const int k = lane;
            float s = 0.f;
#pragma unroll
            for (int m = 0; m < 32; m++) s += S.coef[m] * S.Es[m][k];
            S.vv[k] = s;
        }
        __syncthreads();

        // ---- channel reductions ----
        if (tid < 128) {
            const int h = tid;
            float sq = 0.f, scq = 0.f;
#pragma unroll
            for (int m = 0; m < 32; m++) {
                const float q = S.DQ[b][1][m][h];
                sq  += q;
                scq += S.vv[m] * q;
            }
            S.O[h]         = sq;
            S.O[2 * H + h] = scq;
        } else {
            const int h = tid - 128;
            float sdw = 0.f;
#pragma unroll
            for (int m = 0; m < 32; m++) sdw += S.wv[m] * S.DQ[b][0][m][h];
            S.O[H + h] = sdw;
        }
        __syncthreads();

        if (tid < 128) {
            const int h = tid;
            const float r = (S.O[3 * h] + S.O[3 * h + 1] + S.O[3 * h + 2]) * (1.f / 96.f);
            rst[(size_t)node * H + h] = S.hs[b][h] + r;
        }
        __syncthreads();   // protect O/hs/Es before next iteration reuse
    }
}

// ---------------- precompute: H1 = Wos@Ws2c, H2 = Woc@Wc2s ----------------
__global__ __launch_bounds__(128) void pre1_kernel(
    const float* __restrict__ Wos, const float* __restrict__ Ws2c,
    const float* __restrict__ Woc, const float* __restrict__ Wc2s,
    float* __restrict__ H1, float* __restrict__ H2)
{
    const bool first = blockIdx.x < H;
    const int r = first ? blockIdx.x : blockIdx.x - H;
    const float* U = first ? Wos : Woc;
    const float* V = first ? Ws2c : Wc2s;
    float* Oo = first ? H1 : H2;
    const int j = threadIdx.x;
    float s = 0.f;
#pragma unroll 4
    for (int k = 0; k < H; k++) s += U[r * H + k] * V[k * H + j];
    Oo[r * H + j] = s;
}

// ---------------- precompute: M quadrants ----------------
__global__ __launch_bounds__(128) void pre2_kernel(
    const float* __restrict__ Wos, const float* __restrict__ Woc,
    const float* __restrict__ Ws2c, const float* __restrict__ Wc2s,
    const float* __restrict__ H1, const float* __restrict__ H2,
    float* __restrict__ M)
{
    const int quad = blockIdx.x >> 7;
    const int r = blockIdx.x & 127;
    const int j = threadIdx.x;
    if (quad == 0) {
        float s = 0.f;
#pragma unroll 4
        for (int k = 0; k < H; k++) s += H1[r * H + k] * Wc2s[k * H + j];
        M[r * 256 + j] = 0.34f * Wos[r * H + j] + 0.165f * s;
    } else if (quad == 1) {
        M[r * 256 + 128 + j] = 0.495f * H1[r * H + j];
    } else if (quad == 2) {
        M[(128 + r) * 256 + j] = 0.495f * H2[r * H + j];
    } else {
        float s = 0.f;
#pragma unroll 4
        for (int k = 0; k < H; k++) s += H2[r * H + k] * Ws2c[k * H + j];
        M[(128 + r) * 256 + 128 + j] = 0.34f * Woc[r * H + j] + 0.165f * s;
    }
}

// ---------------- precompute: fused bias c ----------------
__global__ __launch_bounds__(128) void pre3_kernel(
    const float* __restrict__ bos, const float* __restrict__ boc,
    const float* __restrict__ Ws2c, const float* __restrict__ Wc2s,
    float* __restrict__ c)
{
    __shared__ float u[H], v[H];
    const int j = threadIdx.x;
    float su = 0.f, sv = 0.f;
    for (int k = 0; k < H; k++) {
        su += bos[k] * Ws2c[k * H + j];
        sv += boc[k] * Wc2s[k * H + j];
    }
    u[j] = su; v[j] = sv;
    __syncthreads();
    float t1 = 0.f, t2 = 0.f;
    for (int k = 0; k < H; k++) {
        t1 += u[k] * Wc2s[k * H + j];
        t2 += v[k] * Ws2c[k * H + j];
    }
    c[j]       = 0.34f * bos[j] + 0.165f * t1 + 0.495f * v[j];
    c[128 + j] = 0.34f * boc[j] + 0.165f * t2 + 0.495f * u[j];
}

// ---------------- fused final GEMM ----------------
__global__ __launch_bounds__(128) void mix_kernel(
    const float* __restrict__ rst_sim, const float* __restrict__ rst_cor,
    const float* __restrict__ M, const float* __restrict__ c,
    float* __restrict__ out)
{
    __shared__ float xb[256][34];
    const int base = blockIdx.x * 32;
    const int tid = threadIdx.x;

    for (int kk = tid; kk < 256; kk += 128) {
        const float* src = (kk < 128) ? (rst_sim + (size_t)base * H + kk)
                                      : (rst_cor + (size_t)base * H + (kk - 128));
#pragma unroll 4
        for (int r = 0; r < 32; r++) xb[kk][r] = src[r * H];
    }
    __syncthreads();

    const int j0 = tid;
    const int j1 = tid + 128;
    ULL acc0[16], acc1[16];
#pragma unroll
    for (int rp = 0; rp < 16; rp++) { acc0[rp] = 0ULL; acc1[rp] = 0ULL; }

#pragma unroll 2
    for (int k = 0; k < 256; k++) {
        const float w0 = M[k * 256 + j0];
        const float w1 = M[k * 256 + j1];
        const ULL wd0 = pk2(w0, w0);
        const ULL wd1 = pk2(w1, w1);
        const ULL* xp = (const ULL*)&xb[k][0];
#pragma unroll
        for (int rp = 0; rp < 16; rp++) {
            const ULL xv = xp[rp];
            ffma2(acc0[rp], xv, wd0);
            ffma2(acc1[rp], xv, wd1);
        }
    }

    const float c0 = c[j0], c1 = c[j1];
    float* o0 = out + j0;
    float* o1 = out + (size_t)N_DST * H + tid;
#pragma unroll
    for (int rp = 0; rp < 16; rp++) {
        const float2 f0 = upk2(acc0[rp]);
        const float2 f1 = upk2(acc1[rp]);
        o0[(size_t)(base + 2 * rp + 0) * H] = f0.x + c0;
        o0[(size_t)(base + 2 * rp + 1) * H] = f0.y + c0;
        o1[(size_t)(base + 2 * rp + 0) * H] = f1.x + c1;
        o1[(size_t)(base + 2 * rp + 1) * H] = f1.y + c1;
    }
}

// ---------------- launch ----------------
extern "C" void kernel_launch(void* const* d_in, const int* in_sizes, int n_in,
                              void* d_out, int out_size)
{
    const int*   x         = (const int*)d_in[0];
    const int*   neigh_sim = (const int*)d_in[1];
    const int*   neigh_cor = (const int*)d_in[2];
    const float* emb0_sim  = (const float*)d_in[3];
    const float* emb1_sim  = (const float*)d_in[4];
    const float* emb0_cor  = (const float*)d_in[5];
    const float* emb1_cor  = (const float*)d_in[6];
    const float* W_in_sim  = (const float*)d_in[7];
    const float* b_in_sim  = (const float*)d_in[8];
    const float* W_in_cor  = (const float*)d_in[9];
    const float* b_in_cor  = (const float*)d_in[10];
    const float* W_out_sim = (const float*)d_in[11];
    const float* b_out_sim = (const float*)d_in[12];
    const float* W_out_cor = (const float*)d_in[13];
    const float* b_out_cor = (const float*)d_in[14];
    const float* W_sim2cor = (const float*)d_in[15];
    const float* W_cor2sim = (const float*)d_in[16];

    float *feat_sim, *feat_cor, *rst_sim, *rst_cor, *H1, *H2, *M, *c;
    cudaGetSymbolAddress((void**)&feat_sim, g_feat_sim);
    cudaGetSymbolAddress((void**)&feat_cor, g_feat_cor);
    cudaGetSymbolAddress((void**)&rst_sim,  g_rst_sim);
    cudaGetSymbolAddress((void**)&rst_cor,  g_rst_cor);
    cudaGetSymbolAddress((void**)&H1,       g_H1);
    cudaGetSymbolAddress((void**)&H2,       g_H2);
    cudaGetSymbolAddress((void**)&M,        g_M);
    cudaGetSymbolAddress((void**)&c,        g_c);

    float* out = (float*)d_out;

    cudaFuncSetAttribute(attn_kernel, cudaFuncAttributeMaxDynamicSharedMemorySize, ATTN_SMEM);

    pre1_kernel<<<2 * H, 128>>>(W_out_sim, W_sim2cor, W_out_cor, W_cor2sim, H1, H2);
    pre2_kernel<<<4 * H, 128>>>(W_out_sim, W_out_cor, W_sim2cor, W_cor2sim, H1, H2, M);
    pre3_kernel<<<1, 128>>>(b_out_sim, b_out_cor, W_sim2cor, W_cor2sim, c);

    feat_kernel<<<2 * (N_SRC / 64), 128>>>(x,
        emb0_sim, emb1_sim, W_in_sim, b_in_sim, feat_sim,
        emb0_cor, emb1_cor, W_in_cor, b_in_cor, feat_cor);

    attn_kernel<<<2 * (N_DST / NPC), 256, ATTN_SMEM>>>(
        feat_sim, feat_cor, neigh_sim, neigh_cor, rst_sim, rst_cor);

    mix_kernel<<<N_DST / 32, 128>>>(rst_sim, rst_cor, M, c, out);
}